// round 7
// baseline (speedup 1.0000x reference)
#include <cuda_runtime.h>

// HSTU positional encoder — coarse two-phase cp.async, no steady-state barriers.
// out[i,:] = x[i,:]*sqrt(D) + pos_weight[pos_ind(i),:] + ts_weight[ts_ind(i),:]
// D = 512 fp32 (2 KB/row), L = 32768, B = 16, P = 8192, NTB = 2048.

#define D 512
#define ALPHA 22.627416997969522f   // sqrt(512)
#define MAX_POS 8192
#define NTB 2048
#define TIME_BUCKET_INCREMENTS 60.0f

#define ROWS 8                      // rows per CTA
#define HALF 4                      // rows per commit group
#define DYN_SMEM (3 * ROWS * D * 4) // 49152 bytes

__device__ __forceinline__ unsigned smem_u32(const void* p) {
    unsigned a;
    asm("{ .reg .u64 t; cvta.to.shared.u64 t, %1; cvt.u32.u64 %0, t; }"
        : "=r"(a) : "l"(p));
    return a;
}
__device__ __forceinline__ void cp_async16(float* dst, const float* src) {
    asm volatile("cp.async.cg.shared.global [%0], [%1], 16;"
                 :: "r"(smem_u32(dst)), "l"(src) : "memory");
}
__device__ __forceinline__ void cp_commit() {
    asm volatile("cp.async.commit_group;" ::: "memory");
}
template <int N>
__device__ __forceinline__ void cp_wait() {
    asm volatile("cp.async.wait_group %0;" :: "n"(N) : "memory");
}

__global__ __launch_bounds__(128)
void hstu_pos_enc_cg(
    const int* __restrict__ seq_lengths,   // [B]
    const int* __restrict__ seq_offsets,   // [B+1]
    const float* __restrict__ x,           // [L, D]
    const int* __restrict__ num_targets,   // [B]
    const int* __restrict__ seq_ts,        // [L]
    const float* __restrict__ pos_weight,  // [P, D]
    const float* __restrict__ ts_weight,   // [NTB+1, D]
    float* __restrict__ out,               // [L, D]
    int B, int L)
{
    extern __shared__ __align__(16) float dyn[];
    float* sx = dyn;                  // [ROWS][D]
    float* sp = dyn + ROWS * D;       // [ROWS][D]
    float* st = dyn + 2 * ROWS * D;   // [ROWS][D]

    __shared__ int s_pos[ROWS], s_ts[ROWS];
    __shared__ int s_psrc[ROWS], s_tsrc[ROWS];

    const int tid  = threadIdx.x;
    const int base = blockIdx.x * ROWS;

    int n_rows = L - base;
    if (n_rows > ROWS) n_rows = ROWS;
    if (n_rows < 0)    n_rows = 0;

    // ---- index precompute: thread r handles row base+r ----
    if (tid < n_rows) {
        const int row = base + tid;

        int lo = 0, hi = B - 1;
        while (lo < hi) {
            int mid = (lo + hi + 1) >> 1;
            if (seq_offsets[mid] <= row) lo = mid; else hi = mid - 1;
        }
        const int b = lo;

        const int off = seq_offsets[b];
        const int rel_pos = row - off;

        int len = seq_lengths[b]; if (len < 0) len = 0;
        int nt  = num_targets[b]; if (nt  < 0) nt  = 0;
        int high_ind = len - nt;  if (high_ind < 0) high_ind = 0;

        int p = (rel_pos < high_ind) ? rel_pos : high_ind;
        p = high_ind - p;                   // MAX_CONTEXTUAL_SEQ_LEN = 0
        if (p > MAX_POS - 1) p = MAX_POS - 1;
        if (p < 0) p = 0;
        s_pos[tid] = p;

        const int end = seq_offsets[b + 1];
        const float qt = (float)seq_ts[end - 1];
        const float tt = (float)seq_ts[row];
        float dt = qt - tt;                 // TIME_DELTA = 0
        if (dt < 1e-6f) dt = 1e-6f;
        dt = dt / TIME_BUCKET_INCREMENTS;
        const float v = sqrtf(dt);          // TIME_BUCKET_SCALE = 1
        int ti = (int)v;
        if (ti > NTB) ti = NTB;
        s_ts[tid] = ti;
    }
    __syncthreads();

    // ---- dedup: first row in CTA with the same table index ----
    if (tid < n_rows) {
        int ps = tid, tsrc = tid;
        for (int r = tid - 1; r >= 0; r--) {
            if (s_pos[r] == s_pos[tid]) ps  = r;
            if (s_ts[r]  == s_ts[tid])  tsrc = r;
        }
        s_psrc[tid] = ps;
        s_tsrc[tid] = tsrc;
    }
    __syncthreads();

    const int c = tid * 4;   // float offset of this thread's 16B slice

    // ---- issue: two halves, two commit groups ----
    #pragma unroll
    for (int r = 0; r < HALF; r++) {
        if (r < n_rows) {
            cp_async16(&sx[r * D + c], x + (size_t)(base + r) * D + c);
            if (s_psrc[r] == r) cp_async16(&sp[r * D + c], pos_weight + (size_t)s_pos[r] * D + c);
            if (s_tsrc[r] == r) cp_async16(&st[r * D + c], ts_weight  + (size_t)s_ts[r]  * D + c);
        }
    }
    cp_commit();
    #pragma unroll
    for (int r = HALF; r < ROWS; r++) {
        if (r < n_rows) {
            cp_async16(&sx[r * D + c], x + (size_t)(base + r) * D + c);
            if (s_psrc[r] == r) cp_async16(&sp[r * D + c], pos_weight + (size_t)s_pos[r] * D + c);
            if (s_tsrc[r] == r) cp_async16(&st[r * D + c], ts_weight  + (size_t)s_ts[r]  * D + c);
        }
    }
    cp_commit();

    // ---- compute: each thread reads only slices it wrote -> no syncthreads ----
    cp_wait<1>();
    #pragma unroll
    for (int r = 0; r < HALF; r++) {
        if (r < n_rows) {
            const float4 xv = *(const float4*)&sx[r * D + c];
            const float4 pv = *(const float4*)&sp[s_psrc[r] * D + c];
            const float4 tv = *(const float4*)&st[s_tsrc[r] * D + c];
            float4 ov;
            ov.x = fmaf(xv.x, ALPHA, pv.x + tv.x);
            ov.y = fmaf(xv.y, ALPHA, pv.y + tv.y);
            ov.z = fmaf(xv.z, ALPHA, pv.z + tv.z);
            ov.w = fmaf(xv.w, ALPHA, pv.w + tv.w);
            __stcs((float4*)(out + (size_t)(base + r) * D) + tid, ov);
        }
    }
    cp_wait<0>();
    #pragma unroll
    for (int r = HALF; r < ROWS; r++) {
        if (r < n_rows) {
            const float4 xv = *(const float4*)&sx[r * D + c];
            const float4 pv = *(const float4*)&sp[s_psrc[r] * D + c];
            const float4 tv = *(const float4*)&st[s_tsrc[r] * D + c];
            float4 ov;
            ov.x = fmaf(xv.x, ALPHA, pv.x + tv.x);
            ov.y = fmaf(xv.y, ALPHA, pv.y + tv.y);
            ov.z = fmaf(xv.z, ALPHA, pv.z + tv.z);
            ov.w = fmaf(xv.w, ALPHA, pv.w + tv.w);
            __stcs((float4*)(out + (size_t)(base + r) * D) + tid, ov);
        }
    }
}

extern "C" void kernel_launch(void* const* d_in, const int* in_sizes, int n_in,
                              void* d_out, int out_size)
{
    // Input order (metadata): [max_seq_len?], seq_lengths, seq_offsets,
    // seq_embeddings, num_targets, seq_timestamps, pos_weight, ts_weight.
    int o = (n_in == 8) ? 1 : 0;

    const int*   seq_lengths = (const int*)  d_in[o + 0];
    const int*   seq_offsets = (const int*)  d_in[o + 1];
    const float* x           = (const float*)d_in[o + 2];
    const int*   num_targets = (const int*)  d_in[o + 3];
    const int*   seq_ts      = (const int*)  d_in[o + 4];
    const float* pos_weight  = (const float*)d_in[o + 5];
    const float* ts_weight   = (const float*)d_in[o + 6];
    float*       out         = (float*)d_out;

    const int B = in_sizes[o + 0];          // seq_lengths element count
    const int L = out_size / D;             // total token rows

    cudaFuncSetAttribute(hstu_pos_enc_cg,
                         cudaFuncAttributeMaxDynamicSharedMemorySize, DYN_SMEM);

    const int grid = (L + ROWS - 1) / ROWS;
    hstu_pos_enc_cg<<<grid, 128, DYN_SMEM>>>(seq_lengths, seq_offsets, x,
                                             num_targets, seq_ts, pos_weight,
                                             ts_weight, out, B, L);
}

// round 9
// speedup vs baseline: 1.3129x; 1.3129x over previous
#include <cuda_runtime.h>

// HSTU positional encoder — register-MLP, fat CTAs (256 thr, 8 rows) to cut
// cross-CTA L1tex queue contention (oe x MLP_p1 reduction).
// out[i,:] = x[i,:]*sqrt(D) + pos_weight[pos_ind(i),:] + ts_weight[ts_ind(i),:]
// D = 512 fp32, L = 32768, B = 16, P = 8192, NTB = 2048.

#define D 512
#define ALPHA 22.627416997969522f   // sqrt(512)
#define MAX_POS 8192
#define NTB 2048
#define TIME_BUCKET_INCREMENTS 60.0f

#define ROWS 8                      // rows per CTA
#define GR   4                      // rows per 128-thread group

__global__ __launch_bounds__(256)
void hstu_pos_enc_fat(
    const int* __restrict__ seq_lengths,   // [B]
    const int* __restrict__ seq_offsets,   // [B+1]
    const float* __restrict__ x,           // [L, D]
    const int* __restrict__ num_targets,   // [B]
    const int* __restrict__ seq_ts,        // [L]
    const float* __restrict__ pos_weight,  // [P, D]
    const float* __restrict__ ts_weight,   // [NTB+1, D]
    float* __restrict__ out,               // [L, D]
    int B, int L)
{
    __shared__ int s_pos[ROWS];
    __shared__ int s_ts[ROWS];

    const int tid  = threadIdx.x;
    const int base = blockIdx.x * ROWS;

    int n_rows = L - base;
    if (n_rows > ROWS) n_rows = ROWS;
    if (n_rows < 0)    n_rows = 0;

    // ---- index precompute: thread r (<8) handles row base+r ----
    if (tid < n_rows) {
        const int row = base + tid;

        int lo = 0, hi = B - 1;
        while (lo < hi) {
            int mid = (lo + hi + 1) >> 1;
            if (seq_offsets[mid] <= row) lo = mid; else hi = mid - 1;
        }
        const int b = lo;

        const int off = seq_offsets[b];
        const int rel_pos = row - off;

        int len = seq_lengths[b]; if (len < 0) len = 0;
        int nt  = num_targets[b]; if (nt  < 0) nt  = 0;
        int high_ind = len - nt;  if (high_ind < 0) high_ind = 0;

        int p = (rel_pos < high_ind) ? rel_pos : high_ind;
        p = high_ind - p;                   // MAX_CONTEXTUAL_SEQ_LEN = 0
        if (p > MAX_POS - 1) p = MAX_POS - 1;
        if (p < 0) p = 0;
        s_pos[tid] = p;

        const int end = seq_offsets[b + 1];
        const float qt = (float)seq_ts[end - 1];
        const float tt = (float)seq_ts[row];
        float dt = qt - tt;                 // TIME_DELTA = 0
        if (dt < 1e-6f) dt = 1e-6f;
        dt = dt / TIME_BUCKET_INCREMENTS;
        const float v = sqrtf(dt);          // TIME_BUCKET_SCALE = 1
        int ti = (int)v;
        if (ti > NTB) ti = NTB;
        s_ts[tid] = ti;
    }
    __syncthreads();

    // ---- group g handles rows [g*GR, g*GR+GR) ----
    const int g  = tid >> 7;        // 0 or 1
    const int ct = tid & 127;       // slice index within row
    const int r0 = g * GR;

    const float4* xp[GR];
    const float4* pp[GR];
    const float4* tp[GR];
    #pragma unroll
    for (int r = 0; r < GR; r++) {
        const int row = base + r0 + r;
        xp[r] = (const float4*)(x          + (size_t)row           * D) + ct;
        pp[r] = (const float4*)(pos_weight + (size_t)s_pos[r0 + r] * D) + ct;
        tp[r] = (const float4*)(ts_weight  + (size_t)s_ts[r0 + r]  * D) + ct;
    }

    // Batch loads: 12 independent LDG.128 per thread.
    float4 xv[GR], pv[GR], tv[GR];
    #pragma unroll
    for (int r = 0; r < GR; r++) xv[r] = __ldcs(xp[r]);   // stream-once
    #pragma unroll
    for (int r = 0; r < GR; r++) pv[r] = __ldg(pp[r]);
    #pragma unroll
    for (int r = 0; r < GR; r++) tv[r] = __ldg(tp[r]);

    #pragma unroll
    for (int r = 0; r < GR; r++) {
        const int row = base + r0 + r;
        if (row < L) {
            float4 ov;
            ov.x = fmaf(xv[r].x, ALPHA, pv[r].x + tv[r].x);
            ov.y = fmaf(xv[r].y, ALPHA, pv[r].y + tv[r].y);
            ov.z = fmaf(xv[r].z, ALPHA, pv[r].z + tv[r].z);
            ov.w = fmaf(xv[r].w, ALPHA, pv[r].w + tv[r].w);
            __stcs((float4*)(out + (size_t)row * D) + ct, ov);   // stream-once
        }
    }
}

extern "C" void kernel_launch(void* const* d_in, const int* in_sizes, int n_in,
                              void* d_out, int out_size)
{
    // Input order (metadata): [max_seq_len?], seq_lengths, seq_offsets,
    // seq_embeddings, num_targets, seq_timestamps, pos_weight, ts_weight.
    int o = (n_in == 8) ? 1 : 0;

    const int*   seq_lengths = (const int*)  d_in[o + 0];
    const int*   seq_offsets = (const int*)  d_in[o + 1];
    const float* x           = (const float*)d_in[o + 2];
    const int*   num_targets = (const int*)  d_in[o + 3];
    const int*   seq_ts      = (const int*)  d_in[o + 4];
    const float* pos_weight  = (const float*)d_in[o + 5];
    const float* ts_weight   = (const float*)d_in[o + 6];
    float*       out         = (float*)d_out;

    const int B = in_sizes[o + 0];          // seq_lengths element count
    const int L = out_size / D;             // total token rows

    const int grid = (L + ROWS - 1) / ROWS;
    hstu_pos_enc_fat<<<grid, 256>>>(seq_lengths, seq_offsets, x, num_targets,
                                    seq_ts, pos_weight, ts_weight, out, B, L);
}